// round 9
// baseline (speedup 1.0000x reference)
#include <cuda_runtime.h>
#include <cstdint>

// Problem constants (fixed by the dataset)
#define NN   10000
#define EE   320000
#define BB   2
#define CINN 64
#define HID  128
#define COUT 128
#define TEB  128            // edges per tile
#define NROW (BB * NN)      // 20000 output rows
#define NTILE (EE / TEB * BB)   // 5000 tiles: tile t -> pair t>>1, batch t&1

// Scratch (device globals: no allocations allowed)
__device__ float    g_a_dst[(size_t)NN * HID];
__device__ float    g_a_src[(size_t)BB * NN * HID];
__device__ float    g_agg  [(size_t)BB * NN * HID];
__device__ float    g_den  [NN];
__device__ uint32_t g_W2p  [16 * 8 * 32 * 4];   // W2 tf32 b-frags, s-paired (64KB)
__device__ uint32_t g_W3p  [16 * 8 * 32 * 4];   // W3 tf32 b-frags, s-paired (64KB)

__device__ __forceinline__ float gelu_f(float v) {
    return 0.5f * v * (1.0f + erff(v * 0.70710678118654752440f));
}
__device__ __forceinline__ uint32_t f2tf32(float f) {
    uint32_t r; asm("cvt.rna.tf32.f32 %0, %1;" : "=r"(r) : "f"(f)); return r;
}
__device__ __forceinline__ uint32_t smem_u32(const void* p) {
    uint32_t a; asm("{ .reg .u64 t; cvta.to.shared.u64 t, %1; cvt.u32.u64 %0, t; }" : "=r"(a) : "l"(p));
    return a;
}
__device__ __forceinline__ void mma_tf32(float* d, const uint32_t* a, uint32_t b0, uint32_t b1) {
    asm volatile("mma.sync.aligned.m16n8k8.row.col.f32.tf32.tf32.f32 "
                 "{%0,%1,%2,%3}, {%4,%5,%6,%7}, {%8,%9}, {%0,%1,%2,%3};"
                 : "+f"(d[0]), "+f"(d[1]), "+f"(d[2]), "+f"(d[3])
                 : "r"(a[0]), "r"(a[1]), "r"(a[2]), "r"(a[3]), "r"(b0), "r"(b1));
}

#define MBAR_INIT(mbar, cnt) \
    asm volatile("mbarrier.init.shared.b64 [%0], %1;" :: "r"(mbar), "r"((uint32_t)(cnt)) : "memory")
#define MBAR_ARRIVE(mbar) \
    asm volatile("mbarrier.arrive.shared.b64 _, [%0];" :: "r"(mbar) : "memory")
__device__ __forceinline__ void mbar_wait(uint32_t mbar, uint32_t parity) {
    asm volatile(
        "{\n\t.reg .pred P1;\n\t"
        "WAIT_LOOP_%=:\n\t"
        "mbarrier.try_wait.parity.acquire.cta.shared::cta.b64 P1, [%0], %1, 0x989680;\n\t"
        "@P1 bra.uni WAIT_DONE_%=;\n\t"
        "bra.uni WAIT_LOOP_%=;\n\t"
        "WAIT_DONE_%=:\n\t}"
        :: "r"(mbar), "r"(parity) : "memory");
}

// ---------------------------------------------------------------------------
// Prep: pack a 128x128 row-major weight into tf32 B fragments, s-paired.
//   uint4 (t, sp, l) = { b0(2sp), b1(2sp), b0(2sp+1), b1(2sp+1) }
//   b_j(s) = W[k = s*8 + j*4 + (l&3)][n = t*8 + (l>>2)]
// ---------------------------------------------------------------------------
__global__ void wprep_kernel(const float* __restrict__ W, uint32_t* __restrict__ dst) {
    const int idx = blockIdx.x * blockDim.x + threadIdx.x;
    const int q  = idx & 3;
    const int l  = (idx >> 2) & 31;
    const int sp = (idx >> 7) & 7;
    const int t  = idx >> 10;
    const int j  = q & 1;
    const int s  = sp * 2 + (q >> 1);
    const int k  = s * 8 + j * 4 + (l & 3);
    const int n  = t * 8 + (l >> 2);
    dst[idx] = f2tf32(W[k * HID + n]);
}

// ---------------------------------------------------------------------------
// Per-node precompute (also zeroes g_agg / g_den)
// ---------------------------------------------------------------------------
__global__ void precompute_kernel(const float* __restrict__ x, const float* __restrict__ pos,
                                  const float* __restrict__ W1, const float* __restrict__ b1,
                                  const float* __restrict__ Ws, const float* __restrict__ bs,
                                  float* __restrict__ out) {
    const int blk = blockIdx.x;
    const int b   = blk / NN;
    const int n   = blk - b * NN;
    const int t   = threadIdx.x;
    __shared__ float xr[CINN];
    __shared__ float p3[3];
    if (t < CINN) xr[t] = x[(size_t)blk * CINN + t];
    if (t < 3)    p3[t] = pos[n * 3 + t];

    g_agg[(size_t)blk * HID + t] = 0.0f;
    if (b == 0 && t == 0) g_den[n] = 0.0f;
    __syncthreads();

    float s = b1[t];
#pragma unroll
    for (int j = 0; j < 3; ++j) s += p3[j] * W1[(3 + j) * HID + t];
#pragma unroll 8
    for (int c = 0; c < CINN; ++c) s += xr[c] * W1[(6 + c) * HID + t];
    g_a_src[(size_t)blk * HID + t] = s;

    if (b == 0) {
        float d = p3[0] * W1[0 * HID + t] + p3[1] * W1[1 * HID + t] + p3[2] * W1[2 * HID + t];
        g_a_dst[(size_t)n * HID + t] = d;
    }

    float sk = bs[t];
#pragma unroll 8
    for (int c = 0; c < CINN; ++c) sk += xr[c] * Ws[c * COUT + t];
    out[(size_t)blk * COUT + t] = sk;
}

// ---------------------------------------------------------------------------
// Swizzled fragment smem layout (conflict-free write AND read, sector-paired):
//   word(g,s,r,kk) = (g*16+s)*128 + chunk*4 + slot
//     chunk = (r&7)*4 + ((kk&3) ^ (((r&7)>>1)&3))
//     slot  = (r>>3)*2 + (kk>>2)
// Reader lane l: uint4 at frag_chunk_r(l)*4; a = {v.x, v.z, v.y, v.w}.
// ---------------------------------------------------------------------------
__device__ __forceinline__ int frag_chunk_r(int lane) {
    return (lane >> 2) * 4 + ((lane & 3) ^ (((lane >> 2) >> 1) & 3));
}

// ---------------------------------------------------------------------------
// Edge kernel: persistent, warp-specialized, double-buffered.
// 512 threads: warps 0-7 consumers (GEMM+epilogue), 8-15 producers (fill).
// Per tile (128 edges x 1 batch): producer gathers/gelus h1 into A-frag buf,
// consumer runs m128n128 tf32 GEMM + weighted-scatter epilogue.
// SMEM: Abuf[2] 128KB, b2s, ews[2], dsts[2], 4 mbarriers. 1 CTA/SM.
// ---------------------------------------------------------------------------
#define OFF_ABUF  0
#define OFF_B2S   131072
#define OFF_EWS   131584
#define OFF_DSTS  132608
#define OFF_MBAR  133632
#define EDGE_SMEM 133696

__global__ void __launch_bounds__(512, 1)
edge_kernel(const int* __restrict__ eidx, const float* __restrict__ ew,
            const float* __restrict__ b2, int tpb) {
    extern __shared__ char sm[];
    uint32_t* Abuf = (uint32_t*)(sm + OFF_ABUF);    // [2][16 g? -> 8 g x 16 s x 128]
    float*    b2s  = (float*)   (sm + OFF_B2S);
    float*    ews  = (float*)   (sm + OFF_EWS);     // [2][128]
    int*      dsts = (int*)     (sm + OFF_DSTS);    // [2][128]
    const uint32_t mb = smem_u32(sm + OFF_MBAR);    // full0 full1 empty0 empty1
    const int tid = threadIdx.x;

    if (tid == 0) {
        MBAR_INIT(mb + 0,  256);   // full[0]
        MBAR_INIT(mb + 8,  256);   // full[1]
        MBAR_INIT(mb + 16, 256);   // empty[0]
        MBAR_INIT(mb + 24, 256);   // empty[1]
    }
    if (tid < 128) b2s[tid] = b2[tid];
    __syncthreads();

    const int t0   = blockIdx.x * tpb;
    const int tend = min(t0 + tpb, NTILE);

    if (tid >= 256) {
        // ================= PRODUCER (warps 8-15) =================
        const int ptid = tid - 256;
        const int m  = ptid >> 1;                  // row 0..127
        const int h  = ptid & 1;                   // k-half
        const int g  = m >> 4;
        const int r  = m & 15;
        const int r7 = r & 7;
        const int rh = r >> 3;
        const int swz = (r7 >> 1) & 3;
        int offs[4];
#pragma unroll
        for (int j = 0; j < 4; ++j)
            offs[j] = (r7 * 4 + (j ^ swz)) * 4 + rh * 2 + h;

        int stage = 0, phase = 1;
        for (int t = t0; t < tend; ++t) {
            const int pair = t >> 1;
            const int bb   = t & 1;
            const int e0   = pair * TEB;

            mbar_wait(mb + 16 + stage * 8, phase);          // wait empty[stage]

            if (ptid < TEB) {
                const float w = ew[e0 + ptid];
                const int   d = eidx[EE + e0 + ptid];
                ews[stage * 128 + ptid]  = w;
                dsts[stage * 128 + ptid] = d;
                if (bb == 0) atomicAdd(&g_den[d], w);
            }
            const int sv = eidx[e0 + m];
            const int dv = eidx[EE + e0 + m];
            const float4* pd4 = (const float4*)(g_a_dst + (size_t)dv * HID);
            const float4* ps4 = (const float4*)(g_a_src + ((size_t)bb * NN + sv) * HID);
            uint32_t* Ab = Abuf + stage * 16384;
#pragma unroll
            for (int i = 0; i < 16; ++i) {
                const float4 A0 = pd4[2 * i + h];
                const float4 S0 = ps4[2 * i + h];
                uint32_t* rowp = Ab + (g * 16 + i) * 128;
                rowp[offs[0]] = f2tf32(gelu_f(A0.x + S0.x));
                rowp[offs[1]] = f2tf32(gelu_f(A0.y + S0.y));
                rowp[offs[2]] = f2tf32(gelu_f(A0.z + S0.z));
                rowp[offs[3]] = f2tf32(gelu_f(A0.w + S0.w));
            }
            MBAR_ARRIVE(mb + stage * 8);                    // arrive full[stage]
            stage ^= 1; if (stage == 0) phase ^= 1;
        }
    } else {
        // ================= CONSUMER (warps 0-7) =================
        const int lane = tid & 31;
        const int w    = tid >> 5;
        const int wm   = w & 3;
        const int wn   = w >> 2;
        const int ckr  = frag_chunk_r(lane) * 4;
        const uint4* __restrict__ Bg4 = (const uint4*)g_W2p;

        float b2v[8][2];
#pragma unroll
        for (int t = 0; t < 8; ++t) {
            const int c = wn * 64 + t * 8 + (lane & 3) * 2;
            b2v[t][0] = b2s[c];
            b2v[t][1] = b2s[c + 1];
        }

        int stage = 0, phase = 0;
        for (int t = t0; t < tend; ++t) {
            const int bb = t & 1;

            mbar_wait(mb + stage * 8, phase);               // wait full[stage]

            const uint32_t* Ab = Abuf + stage * 16384;
            float acc[2][8][4];
#pragma unroll
            for (int g = 0; g < 2; ++g)
#pragma unroll
                for (int tt = 0; tt < 8; ++tt)
#pragma unroll
                    for (int q = 0; q < 4; ++q) acc[g][tt][q] = 0.0f;

#pragma unroll
            for (int sp = 0; sp < 8; ++sp) {
                const int s0 = sp * 2;
                uint32_t a[2][2][4];
#pragma unroll
                for (int gg = 0; gg < 2; ++gg) {
                    const int g = wm * 2 + gg;
                    const uint4 v0 = *(const uint4*)(Ab + (g * 16 + s0) * 128 + ckr);
                    const uint4 v1 = *(const uint4*)(Ab + (g * 16 + s0 + 1) * 128 + ckr);
                    a[gg][0][0] = v0.x; a[gg][0][1] = v0.z; a[gg][0][2] = v0.y; a[gg][0][3] = v0.w;
                    a[gg][1][0] = v1.x; a[gg][1][1] = v1.z; a[gg][1][2] = v1.y; a[gg][1][3] = v1.w;
                }
#pragma unroll
                for (int tt = 0; tt < 8; ++tt) {
                    const uint4 bv = __ldg(Bg4 + ((wn * 8 + tt) * 8 + sp) * 32 + lane);
                    mma_tf32(acc[0][tt], a[0][0], bv.x, bv.y);
                    mma_tf32(acc[1][tt], a[1][0], bv.x, bv.y);
                    mma_tf32(acc[0][tt], a[0][1], bv.z, bv.w);
                    mma_tf32(acc[1][tt], a[1][1], bv.z, bv.w);
                }
            }

            // Epilogue: w_e * gelu(acc + b2) -> red.global.add.v2 into g_agg
#pragma unroll
            for (int g = 0; g < 2; ++g) {
#pragma unroll
                for (int rh = 0; rh < 2; ++rh) {
                    const int m = wm * 32 + g * 16 + rh * 8 + (lane >> 2);
                    const float wgt = ews[stage * 128 + m];
                    float* base = g_agg + ((size_t)bb * NN + dsts[stage * 128 + m]) * HID;
#pragma unroll
                    for (int tt = 0; tt < 8; ++tt) {
                        const int c = wn * 64 + tt * 8 + (lane & 3) * 2;
                        const float r0 = wgt * gelu_f(acc[g][tt][rh * 2 + 0] + b2v[tt][0]);
                        const float r1 = wgt * gelu_f(acc[g][tt][rh * 2 + 1] + b2v[tt][1]);
                        asm volatile("red.global.add.v2.f32 [%0], {%1,%2};"
                                     :: "l"(base + c), "f"(r0), "f"(r1) : "memory");
                    }
                }
            }
            MBAR_ARRIVE(mb + 16 + stage * 8);               // arrive empty[stage]
            stage ^= 1; if (stage == 0) phase ^= 1;
        }
    }
}

// ---------------------------------------------------------------------------
// Final kernel (mma.sync tf32): out[row] += (agg[row] @ W3 + den*b3)/(den+eps)
// ---------------------------------------------------------------------------
#define FIN_SMEM (65536 + 512 + 512)
__global__ void __launch_bounds__(256, 2)
final_kernel(const float* __restrict__ b3, float* __restrict__ out) {
    extern __shared__ char sm[];
    uint32_t* A_s  = (uint32_t*)sm;
    float*    b3s  = (float*)(sm + 65536);
    float*    dens = (float*)(sm + 66048);
    const int tid = threadIdx.x;
    const int r0  = blockIdx.x * 128;

    if (tid < 128) {
        b3s[tid] = b3[tid];
        const int row = r0 + tid;
        dens[tid] = (row < NROW) ? g_den[row % NN] : 0.0f;
    }

    {
        const int m   = tid >> 1;
        const int h   = tid & 1;
        const int row = r0 + m;
        const bool ok = (row < NROW);
        const int g  = m >> 4;
        const int r  = m & 15;
        const int r7 = r & 7;
        const int rh = r >> 3;
        const int swz = (r7 >> 1) & 3;
        int offs[4];
#pragma unroll
        for (int j = 0; j < 4; ++j)
            offs[j] = (r7 * 4 + (j ^ swz)) * 4 + rh * 2 + h;
        const float4* pa4 = (const float4*)(g_agg + (size_t)(ok ? row : 0) * HID);
#pragma unroll
        for (int i = 0; i < 16; ++i) {
            float4 A0 = pa4[2 * i + h];
            if (!ok) A0 = make_float4(0, 0, 0, 0);
            uint32_t* rowp = A_s + (g * 16 + i) * 128;
            rowp[offs[0]] = f2tf32(A0.x);
            rowp[offs[1]] = f2tf32(A0.y);
            rowp[offs[2]] = f2tf32(A0.z);
            rowp[offs[3]] = f2tf32(A0.w);
        }
    }
    __syncthreads();

    const int lane = tid & 31;
    const int w    = tid >> 5;
    const int wm   = w & 3;
    const int wn   = w >> 2;
    const int ckr  = frag_chunk_r(lane) * 4;
    float acc[2][8][4];
#pragma unroll
    for (int g = 0; g < 2; ++g)
#pragma unroll
        for (int t = 0; t < 8; ++t)
#pragma unroll
            for (int q = 0; q < 4; ++q) acc[g][t][q] = 0.0f;

    const uint4* __restrict__ Bg4 = (const uint4*)g_W3p;

#pragma unroll
    for (int sp = 0; sp < 8; ++sp) {
        const int s0 = sp * 2;
        uint32_t a[2][2][4];
#pragma unroll
        for (int gg = 0; gg < 2; ++gg) {
            const int g = wm * 2 + gg;
            const uint4 v0 = *(const uint4*)(A_s + (g * 16 + s0) * 128 + ckr);
            const uint4 v1 = *(const uint4*)(A_s + (g * 16 + s0 + 1) * 128 + ckr);
            a[gg][0][0] = v0.x; a[gg][0][1] = v0.z; a[gg][0][2] = v0.y; a[gg][0][3] = v0.w;
            a[gg][1][0] = v1.x; a[gg][1][1] = v1.z; a[gg][1][2] = v1.y; a[gg][1][3] = v1.w;
        }
#pragma unroll
        for (int t = 0; t < 8; ++t) {
            const uint4 bv = __ldg(Bg4 + ((wn * 8 + t) * 8 + sp) * 32 + lane);
            mma_tf32(acc[0][t], a[0][0], bv.x, bv.y);
            mma_tf32(acc[1][t], a[1][0], bv.x, bv.y);
            mma_tf32(acc[0][t], a[0][1], bv.z, bv.w);
            mma_tf32(acc[1][t], a[1][1], bv.z, bv.w);
        }
    }

#pragma unroll
    for (int g = 0; g < 2; ++g) {
#pragma unroll
        for (int rh = 0; rh < 2; ++rh) {
            const int m   = wm * 32 + g * 16 + rh * 8 + (lane >> 2);
            const int row = r0 + m;
            if (row < NROW) {
                const float den = dens[m];
                const float inv = 1.0f / (den + 1e-12f);
                float* op = out + (size_t)row * COUT;
#pragma unroll
                for (int t = 0; t < 8; ++t) {
                    const int c = wn * 64 + t * 8 + (lane & 3) * 2;
                    float2 o = *(float2*)(op + c);
                    o.x += (acc[g][t][rh * 2 + 0] + den * b3s[c]) * inv;
                    o.y += (acc[g][t][rh * 2 + 1] + den * b3s[c + 1]) * inv;
                    *(float2*)(op + c) = o;
                }
            }
        }
    }
}

// ---------------------------------------------------------------------------
extern "C" void kernel_launch(void* const* d_in, const int* in_sizes, int n_in,
                              void* d_out, int out_size) {
    const float* x   = (const float*)d_in[0];
    const float* pos = (const float*)d_in[1];
    const int*   ei  = (const int*)  d_in[2];
    const float* ew  = (const float*)d_in[3];
    const float* W1  = (const float*)d_in[4];
    const float* b1  = (const float*)d_in[5];
    const float* W2  = (const float*)d_in[6];
    const float* b2  = (const float*)d_in[7];
    const float* W3  = (const float*)d_in[8];
    const float* b3  = (const float*)d_in[9];
    const float* Ws  = (const float*)d_in[10];
    const float* bs  = (const float*)d_in[11];
    float* out = (float*)d_out;

    uint32_t* w2p; cudaGetSymbolAddress((void**)&w2p, g_W2p);
    uint32_t* w3p; cudaGetSymbolAddress((void**)&w3p, g_W3p);

    int dev = 0, nsm = 148;
    cudaGetDevice(&dev);
    cudaDeviceGetAttribute(&nsm, cudaDevAttrMultiProcessorCount, dev);
    const int grid = nsm;
    const int tpb  = (NTILE + grid - 1) / grid;

    cudaFuncSetAttribute(edge_kernel,  cudaFuncAttributeMaxDynamicSharedMemorySize, EDGE_SMEM);
    cudaFuncSetAttribute(final_kernel, cudaFuncAttributeMaxDynamicSharedMemorySize, FIN_SMEM);

    wprep_kernel<<<64, 256>>>(W2, w2p);
    wprep_kernel<<<64, 256>>>(W3, w3p);
    precompute_kernel<<<NROW, HID>>>(x, pos, W1, b1, Ws, bs, out);
    edge_kernel<<<grid, 512, EDGE_SMEM>>>(ei, ew, b2, tpb);
    final_kernel<<<(NROW + 127) / 128, 256, FIN_SMEM>>>(b3, out);
}

// round 10
// speedup vs baseline: 1.3990x; 1.3990x over previous
#include <cuda_runtime.h>
#include <cstdint>

// Problem constants (fixed by the dataset)
#define NN   10000
#define EE   320000
#define BB   2
#define CINN 64
#define HID  128
#define COUT 128
#define TE   128          // edges per block (= M tile of the edge GEMM)
#define NROW (BB * NN)    // 20000 output rows

// Scratch (device globals: no allocations allowed)
__device__ float    g_a_dst[(size_t)NN * HID];        //  5.12 MB
__device__ float    g_a_src[(size_t)BB * NN * HID];   // 10.24 MB
__device__ float    g_agg  [(size_t)BB * NN * HID];   // 10.24 MB
__device__ float    g_den  [NN];
__device__ uint32_t g_W2p  [16 * 8 * 32 * 4];         // W2 tf32 b-frags, s-paired (64KB)
__device__ uint32_t g_W3p  [16 * 8 * 32 * 4];         // W3 tf32 b-frags, s-paired (64KB)

// Fast branch-free gelu: 0.5x(1+tanh(sqrt(2/pi)(x+0.044715x^3))) with the
// sm_75+ tanh.approx.f32 SFU op. ~7 ops vs ~25+ (branchy) for erff-based.
__device__ __forceinline__ float tanh_ap(float x) {
    float y; asm("tanh.approx.f32 %0, %1;" : "=f"(y) : "f"(x)); return y;
}
__device__ __forceinline__ float gelu_f(float v) {
    const float k0 = 0.7978845608028654f;   // sqrt(2/pi)
    const float k1 = 0.044715f;
    const float u  = k0 * fmaf(k1 * v, v * v, v);
    return 0.5f * v * (1.0f + tanh_ap(u));
}
__device__ __forceinline__ uint32_t f2tf32(float f) {
    uint32_t r; asm("cvt.rna.tf32.f32 %0, %1;" : "=r"(r) : "f"(f)); return r;
}
// mma.sync m16n8k8 tf32 (A row-major frag, B col-major frag, f32 accum)
__device__ __forceinline__ void mma_tf32(float* d, const uint32_t* a, uint32_t b0, uint32_t b1) {
    asm volatile("mma.sync.aligned.m16n8k8.row.col.f32.tf32.tf32.f32 "
                 "{%0,%1,%2,%3}, {%4,%5,%6,%7}, {%8,%9}, {%0,%1,%2,%3};"
                 : "+f"(d[0]), "+f"(d[1]), "+f"(d[2]), "+f"(d[3])
                 : "r"(a[0]), "r"(a[1]), "r"(a[2]), "r"(a[3]), "r"(b0), "r"(b1));
}

// ---------------------------------------------------------------------------
// Prep: pack a 128x128 row-major weight into tf32 B fragments, s-paired.
// uint4 entry (t, sp, l) = { b0(s=2sp), b1(s=2sp), b0(s=2sp+1), b1(s=2sp+1) }
//   b_j(s) = W[k = s*8 + j*4 + (l&3)][n = t*8 + (l>>2)]
// ---------------------------------------------------------------------------
__global__ void wprep_kernel(const float* __restrict__ W, uint32_t* __restrict__ dst) {
    const int idx = blockIdx.x * blockDim.x + threadIdx.x;   // 0..16383 words
    const int q  = idx & 3;
    const int l  = (idx >> 2) & 31;
    const int sp = (idx >> 7) & 7;
    const int t  = idx >> 10;                                 // 0..15
    const int j  = q & 1;
    const int s  = sp * 2 + (q >> 1);
    const int k  = s * 8 + j * 4 + (l & 3);
    const int n  = t * 8 + (l >> 2);
    dst[idx] = f2tf32(W[k * HID + n]);
}

// ---------------------------------------------------------------------------
// Per-node precompute (also zeroes g_agg / g_den):
//   a_dst[n]   = pos[n] @ W1[0:3]
//   a_src[b,n] = pos[n] @ W1[3:6] + x[b,n] @ W1[6:70] + b1
//   out[b,n]   = x[b,n] @ Ws + bs   (skip path; final adds)
// ---------------------------------------------------------------------------
__global__ void precompute_kernel(const float* __restrict__ x, const float* __restrict__ pos,
                                  const float* __restrict__ W1, const float* __restrict__ b1,
                                  const float* __restrict__ Ws, const float* __restrict__ bs,
                                  float* __restrict__ out) {
    const int blk = blockIdx.x;          // b*NN + n
    const int b   = blk / NN;
    const int n   = blk - b * NN;
    const int t   = threadIdx.x;         // 0..127
    __shared__ float xr[CINN];
    __shared__ float p3[3];
    if (t < CINN) xr[t] = x[(size_t)blk * CINN + t];
    if (t < 3)    p3[t] = pos[n * 3 + t];

    g_agg[(size_t)blk * HID + t] = 0.0f;
    if (b == 0 && t == 0) g_den[n] = 0.0f;
    __syncthreads();

    float s = b1[t];
#pragma unroll
    for (int j = 0; j < 3; ++j) s += p3[j] * W1[(3 + j) * HID + t];
#pragma unroll 8
    for (int c = 0; c < CINN; ++c) s += xr[c] * W1[(6 + c) * HID + t];
    g_a_src[(size_t)blk * HID + t] = s;

    if (b == 0) {
        float d = p3[0] * W1[0 * HID + t] + p3[1] * W1[1 * HID + t] + p3[2] * W1[2 * HID + t];
        g_a_dst[(size_t)n * HID + t] = d;
    }

    float sk = bs[t];
#pragma unroll 8
    for (int c = 0; c < CINN; ++c) sk += xr[c] * Ws[c * COUT + t];
    out[(size_t)blk * COUT + t] = sk;
}

// ---------------------------------------------------------------------------
// Swizzled fragment smem layout (conflict-free write AND read, sector-paired):
//   word(g,s,r,kk) = (g*16+s)*128 + chunk*4 + slot
//     chunk = (r&7)*4 + ((kk&3) ^ (((r&7)>>1)&3))   [XOR bank swizzle]
//     slot  = (r>>3)*2 + (kk>>2)
// Reader lane l: uint4 at frag_chunk_r(l)*4; a = {v.x, v.z, v.y, v.w}.
// ---------------------------------------------------------------------------
__device__ __forceinline__ int frag_chunk_r(int lane) {
    return (lane >> 2) * 4 + ((lane & 3) ^ (((lane >> 2) >> 1) & 3));
}

// ---------------------------------------------------------------------------
// Edge kernel (mma.sync tf32). Per block: 128 edges, 256 threads (8 warps).
// SMEM: A frags 64KB + staging -> 2 CTAs/SM (phase overlap).
// ---------------------------------------------------------------------------
#define EDGE_SMEM (65536 + 512 + 512 + 512)
__global__ void __launch_bounds__(256, 2)
edge_kernel(const int* __restrict__ eidx, const float* __restrict__ ew,
            const float* __restrict__ b2) {
    extern __shared__ char sm[];
    uint32_t* A_s  = (uint32_t*)sm;                 // [8 g][16 s][128 words]
    float*    b2s  = (float*)   (sm + 65536);
    float*    ews  = (float*)   (sm + 66048);
    int*      dsts = (int*)     (sm + 66560);
    const int tid = threadIdx.x;
    const int e0  = blockIdx.x * TE;
    const int b   = blockIdx.y;

    if (tid < TE) {
        b2s[tid]  = b2[tid];
        const float w = ew[e0 + tid];
        const int   d = eidx[EE + e0 + tid];
        ews[tid]  = w;
        dsts[tid] = d;
        if (b == 0) atomicAdd(&g_den[d], w);        // fused den kernel
    }

    // Fill A fragments (swizzled, conflict-free, sector-paired gathers).
    {
        const int m  = tid >> 1;                    // edge row 0..127
        const int h  = tid & 1;                     // k-half owned
        const int sv = eidx[e0 + m];
        const int dv = eidx[EE + e0 + m];
        const int g  = m >> 4;
        const int r  = m & 15;
        const int r7 = r & 7;
        const int rh = r >> 3;
        const int swz = (r7 >> 1) & 3;
        int offs[4];
#pragma unroll
        for (int j = 0; j < 4; ++j)
            offs[j] = (r7 * 4 + (j ^ swz)) * 4 + rh * 2 + h;
        const float4* pd4 = (const float4*)(g_a_dst + (size_t)dv * HID);
        const float4* ps4 = (const float4*)(g_a_src + ((size_t)b * NN + sv) * HID);
#pragma unroll
        for (int i = 0; i < 16; ++i) {              // i = s step
            const float4 A0 = pd4[2 * i + h];
            const float4 S0 = ps4[2 * i + h];
            uint32_t* rowp = A_s + (g * 16 + i) * 128;
            rowp[offs[0]] = f2tf32(gelu_f(A0.x + S0.x));
            rowp[offs[1]] = f2tf32(gelu_f(A0.y + S0.y));
            rowp[offs[2]] = f2tf32(gelu_f(A0.z + S0.z));
            rowp[offs[3]] = f2tf32(gelu_f(A0.w + S0.w));
        }
    }
    __syncthreads();

    // GEMM: warp (wm, wn) -> edges [wm*32,+32), cols [wn*64,+64)
    const int lane = tid & 31;
    const int w    = tid >> 5;
    const int wm   = w & 3;
    const int wn   = w >> 2;
    const int ckr  = frag_chunk_r(lane) * 4;
    float acc[2][8][4];
#pragma unroll
    for (int g = 0; g < 2; ++g)
#pragma unroll
        for (int t = 0; t < 8; ++t)
#pragma unroll
            for (int q = 0; q < 4; ++q) acc[g][t][q] = 0.0f;

    const uint4* __restrict__ Bg4 = (const uint4*)g_W2p;

#pragma unroll
    for (int sp = 0; sp < 8; ++sp) {
        const int s0 = sp * 2;
        uint32_t a[2][2][4];
#pragma unroll
        for (int gg = 0; gg < 2; ++gg) {
            const int g = wm * 2 + gg;
            const uint4 v0 = *(const uint4*)(A_s + (g * 16 + s0) * 128 + ckr);
            const uint4 v1 = *(const uint4*)(A_s + (g * 16 + s0 + 1) * 128 + ckr);
            a[gg][0][0] = v0.x; a[gg][0][1] = v0.z; a[gg][0][2] = v0.y; a[gg][0][3] = v0.w;
            a[gg][1][0] = v1.x; a[gg][1][1] = v1.z; a[gg][1][2] = v1.y; a[gg][1][3] = v1.w;
        }
#pragma unroll
        for (int t = 0; t < 8; ++t) {
            const uint4 bv = __ldg(Bg4 + ((wn * 8 + t) * 8 + sp) * 32 + lane);
            mma_tf32(acc[0][t], a[0][0], bv.x, bv.y);
            mma_tf32(acc[1][t], a[1][0], bv.x, bv.y);
            mma_tf32(acc[0][t], a[0][1], bv.z, bv.w);
            mma_tf32(acc[1][t], a[1][1], bv.z, bv.w);
        }
    }

    // Epilogue: D frag (r = lane>>2 (+8), c = 2*(lane&3) (+1)) -> v2 reductions
    float b2v[8][2];
#pragma unroll
    for (int t = 0; t < 8; ++t) {
        const int c = wn * 64 + t * 8 + (lane & 3) * 2;
        b2v[t][0] = b2s[c];
        b2v[t][1] = b2s[c + 1];
    }
#pragma unroll
    for (int g = 0; g < 2; ++g) {
#pragma unroll
        for (int rh = 0; rh < 2; ++rh) {
            const int m   = wm * 32 + g * 16 + rh * 8 + (lane >> 2);
            const float wgt = ews[m];
            float* base = g_agg + ((size_t)b * NN + dsts[m]) * HID;
#pragma unroll
            for (int t = 0; t < 8; ++t) {
                const int c = wn * 64 + t * 8 + (lane & 3) * 2;
                const float r0 = wgt * gelu_f(acc[g][t][rh * 2 + 0] + b2v[t][0]);
                const float r1 = wgt * gelu_f(acc[g][t][rh * 2 + 1] + b2v[t][1]);
                asm volatile("red.global.add.v2.f32 [%0], {%1,%2};"
                             :: "l"(base + c), "f"(r0), "f"(r1) : "memory");
            }
        }
    }
}

// ---------------------------------------------------------------------------
// Final kernel (mma.sync tf32): out[row] += (agg[row] @ W3 + den*b3)/(den+eps)
// 128 rows per block, 256 threads, same fragment machinery (no gather/gelu).
// ---------------------------------------------------------------------------
#define FIN_SMEM (65536 + 512 + 512)
__global__ void __launch_bounds__(256, 2)
final_kernel(const float* __restrict__ b3, float* __restrict__ out) {
    extern __shared__ char sm[];
    uint32_t* A_s  = (uint32_t*)sm;                 // [8 g][16 s][128 words]
    float*    b3s  = (float*)(sm + 65536);
    float*    dens = (float*)(sm + 66048);
    const int tid = threadIdx.x;
    const int r0  = blockIdx.x * 128;

    if (tid < 128) {
        b3s[tid] = b3[tid];
        const int row = r0 + tid;
        dens[tid] = (row < NROW) ? g_den[row % NN] : 0.0f;
    }

    // Fill A fragments from g_agg rows
    {
        const int m   = tid >> 1;
        const int h   = tid & 1;
        const int row = r0 + m;
        const bool ok = (row < NROW);
        const int g  = m >> 4;
        const int r  = m & 15;
        const int r7 = r & 7;
        const int rh = r >> 3;
        const int swz = (r7 >> 1) & 3;
        int offs[4];
#pragma unroll
        for (int j = 0; j < 4; ++j)
            offs[j] = (r7 * 4 + (j ^ swz)) * 4 + rh * 2 + h;
        const float4* pa4 = (const float4*)(g_agg + (size_t)(ok ? row : 0) * HID);
#pragma unroll
        for (int i = 0; i < 16; ++i) {
            float4 A0 = pa4[2 * i + h];
            if (!ok) A0 = make_float4(0, 0, 0, 0);
            uint32_t* rowp = A_s + (g * 16 + i) * 128;
            rowp[offs[0]] = f2tf32(A0.x);
            rowp[offs[1]] = f2tf32(A0.y);
            rowp[offs[2]] = f2tf32(A0.z);
            rowp[offs[3]] = f2tf32(A0.w);
        }
    }
    __syncthreads();

    const int lane = tid & 31;
    const int w    = tid >> 5;
    const int wm   = w & 3;
    const int wn   = w >> 2;
    const int ckr  = frag_chunk_r(lane) * 4;
    float acc[2][8][4];
#pragma unroll
    for (int g = 0; g < 2; ++g)
#pragma unroll
        for (int t = 0; t < 8; ++t)
#pragma unroll
            for (int q = 0; q < 4; ++q) acc[g][t][q] = 0.0f;

    const uint4* __restrict__ Bg4 = (const uint4*)g_W3p;

#pragma unroll
    for (int sp = 0; sp < 8; ++sp) {
        const int s0 = sp * 2;
        uint32_t a[2][2][4];
#pragma unroll
        for (int gg = 0; gg < 2; ++gg) {
            const int g = wm * 2 + gg;
            const uint4 v0 = *(const uint4*)(A_s + (g * 16 + s0) * 128 + ckr);
            const uint4 v1 = *(const uint4*)(A_s + (g * 16 + s0 + 1) * 128 + ckr);
            a[gg][0][0] = v0.x; a[gg][0][1] = v0.z; a[gg][0][2] = v0.y; a[gg][0][3] = v0.w;
            a[gg][1][0] = v1.x; a[gg][1][1] = v1.z; a[gg][1][2] = v1.y; a[gg][1][3] = v1.w;
        }
#pragma unroll
        for (int t = 0; t < 8; ++t) {
            const uint4 bv = __ldg(Bg4 + ((wn * 8 + t) * 8 + sp) * 32 + lane);
            mma_tf32(acc[0][t], a[0][0], bv.x, bv.y);
            mma_tf32(acc[1][t], a[1][0], bv.x, bv.y);
            mma_tf32(acc[0][t], a[0][1], bv.z, bv.w);
            mma_tf32(acc[1][t], a[1][1], bv.z, bv.w);
        }
    }

    // Epilogue: out += (acc + den*b3)/(den+eps)
#pragma unroll
    for (int g = 0; g < 2; ++g) {
#pragma unroll
        for (int rh = 0; rh < 2; ++rh) {
            const int m   = wm * 32 + g * 16 + rh * 8 + (lane >> 2);
            const int row = r0 + m;
            if (row < NROW) {
                const float den = dens[m];
                const float inv = 1.0f / (den + 1e-12f);
                float* op = out + (size_t)row * COUT;
#pragma unroll
                for (int t = 0; t < 8; ++t) {
                    const int c = wn * 64 + t * 8 + (lane & 3) * 2;
                    float2 o = *(float2*)(op + c);
                    o.x += (acc[g][t][rh * 2 + 0] + den * b3s[c]) * inv;
                    o.y += (acc[g][t][rh * 2 + 1] + den * b3s[c + 1]) * inv;
                    *(float2*)(op + c) = o;
                }
            }
        }
    }
}

// ---------------------------------------------------------------------------
extern "C" void kernel_launch(void* const* d_in, const int* in_sizes, int n_in,
                              void* d_out, int out_size) {
    const float* x   = (const float*)d_in[0];
    const float* pos = (const float*)d_in[1];
    const int*   ei  = (const int*)  d_in[2];
    const float* ew  = (const float*)d_in[3];
    const float* W1  = (const float*)d_in[4];
    const float* b1  = (const float*)d_in[5];
    const float* W2  = (const float*)d_in[6];
    const float* b2  = (const float*)d_in[7];
    const float* W3  = (const float*)d_in[8];
    const float* b3  = (const float*)d_in[9];
    const float* Ws  = (const float*)d_in[10];
    const float* bs  = (const float*)d_in[11];
    float* out = (float*)d_out;

    uint32_t* w2p; cudaGetSymbolAddress((void**)&w2p, g_W2p);
    uint32_t* w3p; cudaGetSymbolAddress((void**)&w3p, g_W3p);

    cudaFuncSetAttribute(edge_kernel,  cudaFuncAttributeMaxDynamicSharedMemorySize, EDGE_SMEM);
    cudaFuncSetAttribute(final_kernel, cudaFuncAttributeMaxDynamicSharedMemorySize, FIN_SMEM);

    wprep_kernel<<<64, 256>>>(W2, w2p);
    wprep_kernel<<<64, 256>>>(W3, w3p);
    precompute_kernel<<<NROW, HID>>>(x, pos, W1, b1, Ws, bs, out);
    edge_kernel<<<dim3(EE / TE, BB), 256, EDGE_SMEM>>>(ei, ew, b2);
    final_kernel<<<(NROW + 127) / 128, 256, FIN_SMEM>>>(b3, out);
}